// round 10
// baseline (speedup 1.0000x reference)
#include <cuda_runtime.h>
#include <cuda_fp16.h>
#include <cstdint>
#include <cstddef>

// ============================================================
// Problem constants
// ============================================================
constexpr int N_ACT = 200000;
constexpr int CDIM  = 128;
constexpr int KOFF  = 27;
constexpr float BN_EPS = 1e-4f;

constexpr int BM           = 128;                       // output rows per CTA
constexpr int NBLK         = (N_ACT + BM - 1) / BM;     // 1563
constexpr int CONV_THREADS = 256;                       // 8 warps
constexpr int SUB          = 32;                        // compact subtile rows

// SMEM layout (dynamic) — sized for 2 CTAs/SM (2 x 114944 = 229888)
constexpr uint32_t OFF_ACC  = 0;                        // 128 x 128 fp32, XOR pair swizzle
constexpr uint32_t ACC_B    = 128u * 512u;              // 65536
constexpr uint32_t OFF_A    = OFF_ACC + ACC_B;          // 65536 ; 2 x 32x256 (XOR swizzled)
constexpr uint32_t A_TILE   = 32u * 256u;               // 8192
constexpr uint32_t OFF_B    = OFF_A + 2u * A_TILE;      // 81920 ; 128x256 (XOR swizzled)
constexpr uint32_t B_TILE   = 128u * 256u;              // 32768
constexpr uint32_t OFF_CNT  = OFF_B + B_TILE;           // 114688 ; 27 ints (pad 112)
constexpr uint32_t OFF_WORK = OFF_CNT + 112;            // 114800 ; up to 108 bytes (pad 128)
constexpr uint32_t OFF_NW   = OFF_WORK + 128;           // 114928
constexpr uint32_t SMEM_TOTAL = OFF_NW + 16;            // 114944

// ============================================================
// Device scratch
// ============================================================
__device__ __align__(16) __half g_Af16[(size_t)N_ACT * CDIM];          // 51.2 MB
__device__ __align__(16) __half g_Wt16[(size_t)KOFF * CDIM * CDIM];    // [k][cout][cin]
__device__ int g_cidx[(size_t)NBLK * KOFF * BM];        // compact rulebook (idx | row<<18)
__device__ int g_cnt [NBLK * KOFF];
__device__ float g_psum[NBLK * CDIM];
__device__ float g_psq [NBLK * CDIM];
__device__ __align__(16) float g_scale[CDIM];
__device__ __align__(16) float g_bias [CDIM];

// ============================================================
// Helpers
// ============================================================
__device__ __forceinline__ uint32_t smem_u32(const void* p) {
    uint32_t a;
    asm("{ .reg .u64 t; cvta.to.shared.u64 t, %1; cvt.u32.u64 %0, t; }" : "=r"(a) : "l"(p));
    return a;
}
__device__ __forceinline__ void cp_async16(uint32_t dst, const void* src) {
    asm volatile("cp.async.cg.shared.global [%0], [%1], 16;" :: "r"(dst), "l"(src) : "memory");
}
__device__ __forceinline__ void sts_fill16(uint32_t dst, uint32_t v) {
    asm volatile("st.shared.v4.b32 [%0], {%1, %1, %1, %1};" :: "r"(dst), "r"(v) : "memory");
}
__device__ __forceinline__ void cp_commit() {
    asm volatile("cp.async.commit_group;" ::: "memory");
}
template <int N>
__device__ __forceinline__ void cp_wait() {
    asm volatile("cp.async.wait_group %0;" :: "n"(N) : "memory");
}
__device__ __forceinline__ void ldsm_x4(uint32_t* r, uint32_t addr) {
    asm volatile("ldmatrix.sync.aligned.m8n8.x4.shared.b16 {%0,%1,%2,%3}, [%4];"
                 : "=r"(r[0]), "=r"(r[1]), "=r"(r[2]), "=r"(r[3]) : "r"(addr));
}
__device__ __forceinline__ void mma16816(float* d, const uint32_t* a, const uint32_t* b) {
    asm volatile(
        "mma.sync.aligned.m16n8k16.row.col.f32.f16.f16.f32 "
        "{%0,%1,%2,%3}, {%4,%5,%6,%7}, {%8,%9}, {%0,%1,%2,%3};"
        : "+f"(d[0]), "+f"(d[1]), "+f"(d[2]), "+f"(d[3])
        : "r"(a[0]), "r"(a[1]), "r"(a[2]), "r"(a[3]), "r"(b[0]), "r"(b[1]));
}
// 256B-stride tile swizzle: 16B chunk c (0..15) of row, XOR low3 with row&7.
// Each ldmatrix 128B phase touches 8 consecutive rows at one chunk -> conflict-free.
__device__ __forceinline__ uint32_t swz(int row, int c) {
    return (uint32_t)row * 256u + 16u * (uint32_t)((c & 8) | ((c & 7) ^ (row & 7)));
}
// Accumulator: row r (0..127), pair pp (0..63), XOR bank spread.
__device__ __forceinline__ uint32_t acc_off(int r, int pp) {
    return OFF_ACC + (uint32_t)r * 512u + (uint32_t)((pp ^ (r & 7)) << 3);
}

// ============================================================
// Kernel 1a: features fp32 -> fp16
// ============================================================
__global__ void cvt_features_kernel(const float* __restrict__ f) {
    size_t idx = (size_t)blockIdx.x * blockDim.x + threadIdx.x;
    if (idx >= (size_t)N_ACT * CDIM / 4) return;
    float4 v = reinterpret_cast<const float4*>(f)[idx];
    __half2* dst = reinterpret_cast<__half2*>(g_Af16) + 2 * idx;
    dst[0] = __floats2half2_rn(v.x, v.y);
    dst[1] = __floats2half2_rn(v.z, v.w);
}

// ============================================================
// Kernel 1b: W [k][cin][cout] fp32 -> Wt [k][cout][cin] fp16
// ============================================================
__global__ void cvt_w_kernel(const float* __restrict__ W) {
    int m = blockIdx.x * blockDim.x + threadIdx.x;
    int k   = m >> 14;
    int rem = m & 16383;
    int c   = rem >> 7;   // cout
    int j   = rem & 127;  // cin
    g_Wt16[m] = __float2half_rn(W[(k << 14) + (j << 7) + c]);
}

// ============================================================
// Kernel 1c: build global compact rulebook, one block per (row-block, k)
// ============================================================
__global__ void compact_kernel(const int* __restrict__ nbr) {
    const int b = blockIdx.x;
    const int k = blockIdx.y;
    const int t = threadIdx.x;       // 128 threads
    const int lid = t & 31;
    const int w = t >> 5;            // 4 warps
    __shared__ int wcnt[4];

    int r = b * BM + t;
    int idx = (r < N_ACT) ? nbr[(size_t)k * N_ACT + r] : -1;
    bool valid = (idx >= 0);
    unsigned bal = __ballot_sync(0xFFFFFFFFu, valid);
    if (lid == 0) wcnt[w] = __popc(bal);
    __syncthreads();
    int base = 0;
    #pragma unroll
    for (int j = 0; j < 4; j++) base += (j < w) ? wcnt[j] : 0;
    int pos = base + __popc(bal & ((1u << lid) - 1u));
    if (valid) g_cidx[((size_t)b * KOFF + k) * BM + pos] = idx | (t << 18);
    if (t == 0) g_cnt[b * KOFF + k] = wcnt[0] + wcnt[1] + wcnt[2] + wcnt[3];
}

// ============================================================
// Kernel 2: compacted sparse conv; 2 CTAs/SM, smem fp32 accumulator
// ============================================================
__global__ void __launch_bounds__(CONV_THREADS)
conv_kernel(float* __restrict__ out) {
    extern __shared__ char smem[];
    const uint32_t sb = smem_u32(smem);
    const int tid = threadIdx.x;
    const int wid = tid >> 5;
    const int lid = tid & 31;
    const int b = blockIdx.x;
    const int row0 = b * BM;

    int* s_cnt = reinterpret_cast<int*>(smem + OFF_CNT);
    uint8_t* s_work = reinterpret_cast<uint8_t*>(smem + OFF_WORK);
    int* s_nw = reinterpret_cast<int*>(smem + OFF_NW);

    // ---- zero the smem accumulator (16384 floats) + load cnts ----
    {
        float4* a4 = reinterpret_cast<float4*>(smem + OFF_ACC);
        #pragma unroll
        for (int i = 0; i < 16; i++)
            a4[tid + i * CONV_THREADS] = make_float4(0.f, 0.f, 0.f, 0.f);
    }
    if (tid < KOFF) s_cnt[tid] = g_cnt[b * KOFF + tid];
    __syncthreads();
    if (tid == 0) {
        int nw = 0;
        for (int k = 0; k < KOFF; k++) {
            int ns = (s_cnt[k] + SUB - 1) / SUB;
            for (int s = 0; s < ns; s++) s_work[nw++] = (uint8_t)((k << 2) | s);
        }
        *s_nw = nw;
    }
    __syncthreads();
    const int nwork = *s_nw;

    // ---- tile loaders ----
    // A: 32 gathered rows x 256B; thread -> (row p = tid>>3, chunks o and o+8)
    auto load_A = [&](int u, int buf) {
        int e = s_work[u];
        int k = e >> 2, s = e & 3;
        int cnt = s_cnt[k];
        int p = tid >> 3;
        int o = tid & 7;
        uint32_t dst0 = sb + OFF_A + (uint32_t)buf * A_TILE + swz(p, o);
        uint32_t dst1 = sb + OFF_A + (uint32_t)buf * A_TILE + swz(p, o + 8);
        int pos = s * SUB + p;
        if (pos < cnt) {
            uint32_t ent = (uint32_t)__ldg(&g_cidx[((size_t)b * KOFF + k) * BM + pos]);
            const char* src = (const char*)g_Af16 + (size_t)(ent & 0x3FFFFu) * 256 + o * 16;
            cp_async16(dst0, src);
            cp_async16(dst1, src + 128);
        } else {
            sts_fill16(dst0, 0u);
            sts_fill16(dst1, 0u);
        }
    };
    // B: 128 rows x 256B; thread -> (row n = tid>>1, 8 chunks)
    auto load_B = [&](int k) {
        int n = tid >> 1;
        int half = tid & 1;
        const char* src = (const char*)g_Wt16 + ((size_t)k * 128 + n) * 256 + half * 128;
        uint32_t base = sb + OFF_B + (uint32_t)n * 256u + (uint32_t)half * 128u;
        uint32_t x = (uint32_t)(n & 7) * 16u;
        #pragma unroll
        for (int j = 0; j < 8; j++)
            cp_async16(base + (((uint32_t)j * 16u) ^ x), src + j * 16);
    };

    // ---- per-lane fragment pieces (8 warps: 1M x 8N, warp tile 32x16) ----
    const int ng = wid;
    const int a_r0 = lid & 15;
    const int a_cs = lid >> 4;                         // chunk select (0/1)
    const int b_r  = ng * 16 + (lid & 7) + ((lid & 16) ? 8 : 0);
    const int b_cs = (lid >> 3) & 1;
    const int p_base  = lid >> 2;                      // compact row base in subtile
    const int pp_base = ng * 8 + (lid & 3);            // acc pair base

    // ---- prime: B(k0), A(unit 0) in one group ----
    load_B(s_work[0] >> 2);
    load_A(0, 0);
    cp_commit();

    #pragma unroll 1
    for (int u = 0; u < nwork; u++) {
        const int e = s_work[u];
        const int k = e >> 2, s = e & 3;
        const int buf = u & 1;
        const int cnt = s_cnt[k];
        const int knext = (u + 1 < nwork) ? (s_work[u + 1] >> 2) : -1;

        // prefetch A(u+1), then wait for A(u) (commit order drains boundary-B too)
        if (u + 1 < nwork) {
            load_A(u + 1, buf ^ 1);
            cp_commit();
            cp_wait<1>();
        } else {
            cp_wait<0>();
        }
        __syncthreads();   // S1: tiles visible; prior scatter complete

        // ---- 32x128x128 compact GEMM (warp tile 32x16) ----
        float facc[2][2][4];
        #pragma unroll
        for (int a = 0; a < 2; a++)
            #pragma unroll
            for (int bb2 = 0; bb2 < 2; bb2++)
                #pragma unroll
                for (int c = 0; c < 4; c++) facc[a][bb2][c] = 0.f;
        {
            const uint32_t ab = sb + OFF_A + (uint32_t)buf * A_TILE;
            const uint32_t bbs = sb + OFF_B;
            #pragma unroll
            for (int ks = 0; ks < 8; ks++) {
                uint32_t af0[4], af1[4], t[4];
                int ca = ks * 2 + a_cs;
                int cb = ks * 2 + b_cs;
                ldsm_x4(af0, ab + swz(a_r0, ca));
                ldsm_x4(af1, ab + swz(a_r0 + 16, ca));
                ldsm_x4(t, bbs + swz(b_r, cb));
                uint32_t bf0[2] = {t[0], t[1]};
                uint32_t bf1[2] = {t[2], t[3]};
                mma16816(facc[0][0], af0, bf0);
                mma16816(facc[0][1], af0, bf1);
                mma16816(facc[1][0], af1, bf0);
                mma16816(facc[1][1], af1, bf1);
            }
        }
        __syncthreads();   // S2: all warps done reading A(u) and B(k)

        // at k boundary: start B(knext) (overlaps scatter)
        if (knext >= 0 && knext != k) {
            load_B(knext);
            cp_commit();
        }

        // ---- direct scatter-add into smem accumulator ----
        {
            const int base_s = s * SUB;
            #pragma unroll
            for (int mf = 0; mf < 2; mf++)
                #pragma unroll
                for (int h = 0; h < 2; h++) {
                    int pos = base_s + p_base + mf * 16 + h * 8;
                    if (pos < cnt) {
                        int r = ((uint32_t)g_cidx[((size_t)b * KOFF + k) * BM + pos]) >> 18;
                        #pragma unroll
                        for (int nf = 0; nf < 2; nf++) {
                            uint32_t ad = acc_off(r, pp_base + nf * 4);
                            float2 v = *reinterpret_cast<float2*>(smem + ad);
                            v.x += facc[mf][nf][2 * h];
                            v.y += facc[mf][nf][2 * h + 1];
                            *reinterpret_cast<float2*>(smem + ad) = v;
                        }
                    }
                }
        }
    }
    __syncthreads();   // final scatter complete

    // ---- epilogue: smem acc -> out, + BN partials ----
    {
        const int pp = tid & 63;     // pair (2 channels)
        const int g  = tid >> 6;     // row group 0..3 (32 rows each)
        float s0 = 0.f, s1 = 0.f, q0 = 0.f, q1 = 0.f;
        #pragma unroll 4
        for (int rr = 0; rr < 32; rr++) {
            int r = g * 32 + rr;
            float2 v = *reinterpret_cast<float2*>(smem + acc_off(r, pp));
            int row = row0 + r;
            if (row < N_ACT)
                *reinterpret_cast<float2*>(out + (size_t)row * CDIM + pp * 2) = v;
            s0 += v.x; s1 += v.y;
            q0 = fmaf(v.x, v.x, q0);
            q1 = fmaf(v.y, v.y, q1);
        }
        __syncthreads();
        float4* red = reinterpret_cast<float4*>(smem + OFF_A);   // [4][64]
        red[g * 64 + pp] = make_float4(s0, s1, q0, q1);
        __syncthreads();
        if (tid < 64) {
            float ts0 = 0.f, ts1 = 0.f, tq0 = 0.f, tq1 = 0.f;
            #pragma unroll
            for (int gg = 0; gg < 4; gg++) {
                float4 v = red[gg * 64 + tid];
                ts0 += v.x; ts1 += v.y; tq0 += v.z; tq1 += v.w;
            }
            g_psum[b * CDIM + tid * 2]     = ts0;
            g_psum[b * CDIM + tid * 2 + 1] = ts1;
            g_psq [b * CDIM + tid * 2]     = tq0;
            g_psq [b * CDIM + tid * 2 + 1] = tq1;
        }
    }
}

// ============================================================
// Kernel 3: finalize BN scale/bias (parallel, deterministic tree)
// ============================================================
__global__ void bn_final_kernel(const float* __restrict__ gamma, const float* __restrict__ beta) {
    __shared__ float ss[256], sq[256];
    int c = blockIdx.x;
    int t = threadIdx.x;
    float s = 0.f, q = 0.f;
    for (int b = t; b < NBLK; b += 256) {
        s += g_psum[b * CDIM + c];
        q += g_psq [b * CDIM + c];
    }
    ss[t] = s; sq[t] = q;
    __syncthreads();
    #pragma unroll
    for (int st = 128; st > 0; st >>= 1) {
        if (t < st) { ss[t] += ss[t + st]; sq[t] += sq[t + st]; }
        __syncthreads();
    }
    if (t == 0) {
        float mean = ss[0] / (float)N_ACT;
        float var  = sq[0] / (float)N_ACT - mean * mean;
        float sc   = gamma[c] * rsqrtf(var + BN_EPS);
        g_scale[c] = sc;
        g_bias[c]  = beta[c] - mean * sc;
    }
}

// ============================================================
// Kernel 4: apply BN + ReLU elementwise
// ============================================================
__global__ void bn_apply_kernel(float* __restrict__ out) {
    size_t idx = (size_t)blockIdx.x * blockDim.x + threadIdx.x;
    if (idx >= (size_t)N_ACT * CDIM / 4) return;
    int c4 = (int)(idx & 31);
    float4 v  = reinterpret_cast<float4*>(out)[idx];
    float4 sc = reinterpret_cast<float4*>(g_scale)[c4];
    float4 bi = reinterpret_cast<float4*>(g_bias)[c4];
    v.x = fmaxf(fmaf(v.x, sc.x, bi.x), 0.f);
    v.y = fmaxf(fmaf(v.y, sc.y, bi.y), 0.f);
    v.z = fmaxf(fmaf(v.z, sc.z, bi.z), 0.f);
    v.w = fmaxf(fmaf(v.w, sc.w, bi.w), 0.f);
    reinterpret_cast<float4*>(out)[idx] = v;
}

// ============================================================
// Launch
// ============================================================
extern "C" void kernel_launch(void* const* d_in, const int* in_sizes, int n_in,
                              void* d_out, int out_size) {
    const float* features = (const float*)d_in[0];
    const int*   nbr      = (const int*)d_in[1];
    const float* W        = (const float*)d_in[2];
    const float* gamma    = (const float*)d_in[3];
    const float* beta     = (const float*)d_in[4];
    float* out = (float*)d_out;

    cudaFuncSetAttribute((const void*)conv_kernel,
                         cudaFuncAttributeMaxDynamicSharedMemorySize, SMEM_TOTAL);

    const int chunks = N_ACT * CDIM / 4;
    cvt_features_kernel<<<(chunks + 255) / 256, 256>>>(features);
    cvt_w_kernel<<<KOFF * CDIM * CDIM / 256, 256>>>(W);
    compact_kernel<<<dim3(NBLK, KOFF), 128>>>(nbr);
    conv_kernel<<<NBLK, CONV_THREADS, SMEM_TOTAL>>>(out);
    bn_final_kernel<<<CDIM, 256>>>(gamma, beta);
    bn_apply_kernel<<<(chunks + 255) / 256, 256>>>(out);
}

// round 11
// speedup vs baseline: 1.3699x; 1.3699x over previous
#include <cuda_runtime.h>
#include <cuda_fp16.h>
#include <cstdint>
#include <cstddef>

// ============================================================
// Problem constants
// ============================================================
constexpr int N_ACT = 200000;
constexpr int CDIM  = 128;
constexpr int KOFF  = 27;
constexpr float BN_EPS = 1e-4f;

constexpr int BM           = 256;                       // output rows per CTA
constexpr int NBLK         = (N_ACT + BM - 1) / BM;     // 782
constexpr int CONV_THREADS = 512;                       // 16 warps

// SMEM layout (dynamic)
constexpr uint32_t ROWB     = 272;                      // fp16 tile row stride (conflict-free ldmatrix)
constexpr uint32_t OFF_ACC  = 0;                        // 256 x 128 fp32, rotated pairs (512B rows)
constexpr uint32_t ACC_B    = 256u * 512u;              // 131072
constexpr uint32_t OFF_A    = OFF_ACC + ACC_B;          // 131072 ; 2 x 64x272
constexpr uint32_t A_TILE   = 64u * ROWB;               // 17408
constexpr uint32_t OFF_B    = OFF_A + 2u * A_TILE;      // 165888 ; 128x272 single buffer
constexpr uint32_t B_TILE   = 128u * ROWB;              // 34816
constexpr uint32_t OFF_CIDX = OFF_B + B_TILE;           // 200704 ; 27*256 packed (idx | row<<18)
constexpr uint32_t OFF_WCNT = OFF_CIDX + 27648;         // 228352 ; 27*8 int warp popc
constexpr uint32_t OFF_CNT  = OFF_WCNT + 864;           // 229216 ; 27 ints (pad 112)
constexpr uint32_t OFF_WORK = OFF_CNT + 112;            // 229328 ; 112 ints
constexpr uint32_t OFF_NW   = OFF_WORK + 448;           // 229776
constexpr uint32_t SMEM_TOTAL = OFF_NW + 16;            // 229792  (< 232448 limit)

constexpr int NENT  = KOFF * 256;                       // 6912 rulebook entries
constexpr int NPASS = (NENT + CONV_THREADS - 1) / CONV_THREADS;   // 14

// ============================================================
// Device scratch
// ============================================================
__device__ __align__(16) __half g_Af16[(size_t)N_ACT * CDIM];          // 51.2 MB
__device__ __align__(16) __half g_Wt16[(size_t)KOFF * CDIM * CDIM];    // [k][cout][cin]
__device__ float g_psum[NBLK * CDIM];
__device__ float g_psq [NBLK * CDIM];
__device__ __align__(16) float g_scale[CDIM];
__device__ __align__(16) float g_bias [CDIM];

// ============================================================
// Helpers
// ============================================================
__device__ __forceinline__ uint32_t smem_u32(const void* p) {
    uint32_t a;
    asm("{ .reg .u64 t; cvta.to.shared.u64 t, %1; cvt.u32.u64 %0, t; }" : "=r"(a) : "l"(p));
    return a;
}
__device__ __forceinline__ void cp_async16(uint32_t dst, const void* src) {
    asm volatile("cp.async.cg.shared.global [%0], [%1], 16;" :: "r"(dst), "l"(src) : "memory");
}
__device__ __forceinline__ void sts_fill16(uint32_t dst, uint32_t v) {
    asm volatile("st.shared.v4.b32 [%0], {%1, %1, %1, %1};" :: "r"(dst), "r"(v) : "memory");
}
__device__ __forceinline__ void cp_commit() {
    asm volatile("cp.async.commit_group;" ::: "memory");
}
template <int N>
__device__ __forceinline__ void cp_wait() {
    asm volatile("cp.async.wait_group %0;" :: "n"(N) : "memory");
}
__device__ __forceinline__ void ldsm_x4(uint32_t* r, uint32_t addr) {
    asm volatile("ldmatrix.sync.aligned.m8n8.x4.shared.b16 {%0,%1,%2,%3}, [%4];"
                 : "=r"(r[0]), "=r"(r[1]), "=r"(r[2]), "=r"(r[3]) : "r"(addr));
}
__device__ __forceinline__ void mma16816(float* d, const uint32_t* a, const uint32_t* b) {
    asm volatile(
        "mma.sync.aligned.m16n8k16.row.col.f32.f16.f16.f32 "
        "{%0,%1,%2,%3}, {%4,%5,%6,%7}, {%8,%9}, {%0,%1,%2,%3};"
        : "+f"(d[0]), "+f"(d[1]), "+f"(d[2]), "+f"(d[3])
        : "r"(a[0]), "r"(a[1]), "r"(a[2]), "r"(a[3]), "r"(b[0]), "r"(b[1]));
}
// Accumulator address: row r (0..255), pair index pp (0..63).
// Rotated pair index ((pp + 8r) mod 64): each row's 64B scatter window moves
// across the full 512B row -> scatter banks spread over all 32 banks.
__device__ __forceinline__ uint32_t acc_off(int r, int pp) {
    return OFF_ACC + (uint32_t)r * 512u + (uint32_t)(((pp + r * 8) & 63) << 3);
}

// ============================================================
// Kernel 1a: features fp32 -> fp16
// ============================================================
__global__ void cvt_features_kernel(const float* __restrict__ f) {
    size_t idx = (size_t)blockIdx.x * blockDim.x + threadIdx.x;
    if (idx >= (size_t)N_ACT * CDIM / 4) return;
    float4 v = reinterpret_cast<const float4*>(f)[idx];
    __half2* dst = reinterpret_cast<__half2*>(g_Af16) + 2 * idx;
    dst[0] = __floats2half2_rn(v.x, v.y);
    dst[1] = __floats2half2_rn(v.z, v.w);
}

// ============================================================
// Kernel 1b: W [k][cin][cout] fp32 -> Wt [k][cout][cin] fp16
// ============================================================
__global__ void cvt_w_kernel(const float* __restrict__ W) {
    int m = blockIdx.x * blockDim.x + threadIdx.x;
    int k   = m >> 14;
    int rem = m & 16383;
    int c   = rem >> 7;   // cout
    int j   = rem & 127;  // cin
    g_Wt16[m] = __float2half_rn(W[(k << 14) + (j << 7) + c]);
}

// ============================================================
// Dummy kernel (slot-shifter so ncu captures conv_kernel)
// ============================================================
__global__ void dummy_kernel() {}

// ============================================================
// Kernel 2: compacted sparse conv; smem fp32 accumulator (R9 base)
// ============================================================
__global__ void __launch_bounds__(CONV_THREADS, 1)
conv_kernel(const int* __restrict__ nbr, float* __restrict__ out) {
    extern __shared__ char smem[];
    const uint32_t sb = smem_u32(smem);
    const int tid = threadIdx.x;
    const int wid = tid >> 5;
    const int lid = tid & 31;
    const int row0 = blockIdx.x * BM;

    int* s_cidx = reinterpret_cast<int*>(smem + OFF_CIDX);
    int* s_wcnt = reinterpret_cast<int*>(smem + OFF_WCNT);   // [27][8]
    int* s_cnt  = reinterpret_cast<int*>(smem + OFF_CNT);
    int* s_work = reinterpret_cast<int*>(smem + OFF_WORK);
    int* s_nw   = reinterpret_cast<int*>(smem + OFF_NW);

    // ---- zero the smem accumulator (32768 floats) ----
    {
        float4* a4 = reinterpret_cast<float4*>(smem + OFF_ACC);
        #pragma unroll
        for (int i = 0; i < 16; i++)
            a4[tid + i * CONV_THREADS] = make_float4(0.f, 0.f, 0.f, 0.f);
    }

    // ---- prefetch this CTA's nbr block (27 x 256 int32) ----
    for (int c = tid; c < KOFF * 64; c += CONV_THREADS) {   // 16B chunks (4 rows each)
        int k   = c >> 6;
        int off = (c & 63) * 16;
        int rL  = row0 + (off >> 2) + 3;
        uint32_t dst = sb + OFF_CIDX + (uint32_t)c * 16u;
        if (rL < N_ACT)
            cp_async16(dst, (const char*)(nbr + (size_t)k * N_ACT + row0) + off);
        else
            sts_fill16(dst, 0xFFFFFFFFu);
    }
    cp_commit();
    cp_wait<0>();
    __syncthreads();

    // ---- compaction pass 1: per-warp popc of valid entries (values in regs) ----
    int vreg[NPASS];
    #pragma unroll
    for (int p = 0; p < NPASS; p++) {
        int e = tid + p * CONV_THREADS;
        int v = (e < NENT) ? s_cidx[e] : -1;
        vreg[p] = v;
        unsigned bal = __ballot_sync(0xFFFFFFFFu, v >= 0);
        if (lid == 0 && e < NENT) s_wcnt[(e >> 8) * 8 + ((e >> 5) & 7)] = __popc(bal);
    }
    __syncthreads();

    // ---- compaction pass 2: scan + write packed (idx | row<<18) compact lists ----
    #pragma unroll
    for (int p = 0; p < NPASS; p++) {
        int e = tid + p * CONV_THREADS;
        if (e < NENT) {
            int v = vreg[p];
            unsigned bal = __ballot_sync(0xFFFFFFFFu, v >= 0);
            int seg = e >> 8;
            int wis = (e >> 5) & 7;
            int base = 0;
            #pragma unroll
            for (int j = 0; j < 8; j++) base += (j < wis) ? s_wcnt[seg * 8 + j] : 0;
            int pos = base + __popc(bal & ((1u << lid) - 1u));
            if (v >= 0) s_cidx[seg * 256 + pos] = v | ((e & 255) << 18);
            if ((e & 255) == 0) {
                int tot = 0;
                #pragma unroll
                for (int j = 0; j < 8; j++) tot += s_wcnt[seg * 8 + j];
                s_cnt[seg] = tot;
            }
        }
    }
    __syncthreads();

    // ---- build (k, subtile) work list ----
    if (tid == 0) {
        int nw = 0;
        for (int k = 0; k < KOFF; k++) {
            int ns = (s_cnt[k] + 63) >> 6;
            for (int s = 0; s < ns; s++) s_work[nw++] = (k << 4) | s;
        }
        *s_nw = nw;
    }
    __syncthreads();
    const int nwork = *s_nw;

    // ---- tile loaders (cnt-gated zero-fill; no global sentinel) ----
    auto load_A = [&](int w, int buf) {
        int e = s_work[w];
        int k = e >> 4, s = e & 15;
        int cnt = s_cnt[k];
        int p = tid >> 3;          // compact slot 0..63
        int o = tid & 7;           // 16B chunk
        uint32_t dst = sb + OFF_A + (uint32_t)buf * A_TILE + (uint32_t)p * ROWB + (uint32_t)o * 16u;
        int pos = s * 64 + p;
        if (pos < cnt) {
            uint32_t ent = (uint32_t)s_cidx[k * 256 + pos];
            const char* src = (const char*)g_Af16 + (size_t)(ent & 0x3FFFFu) * 256 + o * 16;
            cp_async16(dst, src);
            cp_async16(dst + 128u, src + 128);
        } else {
            sts_fill16(dst, 0u);
            sts_fill16(dst + 128u, 0u);
        }
    };
    auto load_B = [&](int k) {
        int n = tid >> 2;
        int q = tid & 3;
        uint32_t dst = sb + OFF_B + (uint32_t)n * ROWB + (uint32_t)q * 64u;
        const char* src = (const char*)g_Wt16 + ((size_t)k * 128 + n) * 256 + (size_t)q * 64;
        #pragma unroll
        for (int c = 0; c < 4; c++)
            cp_async16(dst + c * 16u, src + c * 16);
    };

    // ---- per-lane fragment pieces (16 warps: 2M x 8N, warp tile 32x16) ----
    const int mg = wid & 1;
    const int ng = wid >> 1;
    const uint32_t a_row2 = (uint32_t)(mg * 32 + (lid & 15));
    const uint32_t a_coff = (uint32_t)(lid >> 4) * 16u;
    const uint32_t b_row2 = (uint32_t)(ng * 16 + (lid & 7) + ((lid & 16) ? 8 : 0));
    const uint32_t b_coff = (uint32_t)((lid >> 3) & 1) * 16u;
    const int p_base  = mg * 32 + (lid >> 2);
    const int pp_base = ng * 8 + (lid & 3);

    // ---- prime: B(k0), A(unit 0) in one group ----
    load_B(s_work[0] >> 4);
    load_A(0, 0);
    cp_commit();

    #pragma unroll 1
    for (int w = 0; w < nwork; w++) {
        const int e = s_work[w];
        const int k = e >> 4, s = e & 15;
        const int buf = w & 1;
        const int cnt = s_cnt[k];
        const int knext = (w + 1 < nwork) ? (s_work[w + 1] >> 4) : -1;

        // prefetch A(w+1) into the other buffer, then wait for A(w)
        // (groups complete in order; wait<1> also drains any earlier boundary-B group)
        if (w + 1 < nwork) {
            load_A(w + 1, buf ^ 1);
            cp_commit();
            cp_wait<1>();
        } else {
            cp_wait<0>();
        }
        __syncthreads();   // S1: tiles visible; prior scatter complete

        // ---- 64x128x128 compact GEMM (warp tile 32x16) ----
        float facc[2][2][4];
        #pragma unroll
        for (int a = 0; a < 2; a++)
            #pragma unroll
            for (int b = 0; b < 2; b++)
                #pragma unroll
                for (int c = 0; c < 4; c++) facc[a][b][c] = 0.f;
        {
            const uint32_t ab = sb + OFF_A + (uint32_t)buf * A_TILE;
            const uint32_t bb = sb + OFF_B;
            #pragma unroll
            for (int ks = 0; ks < 8; ks++) {
                uint32_t af0[4], af1[4], t[4];
                ldsm_x4(af0, ab + a_row2 * ROWB + (uint32_t)ks * 32u + a_coff);
                ldsm_x4(af1, ab + (a_row2 + 16u) * ROWB + (uint32_t)ks * 32u + a_coff);
                ldsm_x4(t,   bb + b_row2 * ROWB + (uint32_t)ks * 32u + b_coff);
                uint32_t bf0[2] = {t[0], t[1]};
                uint32_t bf1[2] = {t[2], t[3]};
                mma16816(facc[0][0], af0, bf0);
                mma16816(facc[0][1], af0, bf1);
                mma16816(facc[1][0], af1, bf0);
                mma16816(facc[1][1], af1, bf1);
            }
        }

        // S2 only when the B buffer must be recycled (k boundary);
        // A(w)'s buffer is protected by S1 at unit w+1 before load_A(w+2).
        if (knext >= 0 && knext != k) {
            __syncthreads();   // all warps done reading B(k)
            load_B(knext);
            cp_commit();
        }

        // ---- direct scatter-add into smem accumulator (rotated banks) ----
        {
            const int base_s = s * 64;
            #pragma unroll
            for (int mf = 0; mf < 2; mf++)
                #pragma unroll
                for (int h = 0; h < 2; h++) {
                    int pos = base_s + p_base + mf * 16 + h * 8;
                    if (pos < cnt) {
                        int r = ((uint32_t)s_cidx[k * 256 + pos]) >> 18;
                        #pragma unroll
                        for (int nf = 0; nf < 2; nf++) {
                            uint32_t ad = acc_off(r, pp_base + nf * 4);
                            float2 v = *reinterpret_cast<float2*>(smem + ad);
                            v.x += facc[mf][nf][2 * h];
                            v.y += facc[mf][nf][2 * h + 1];
                            *reinterpret_cast<float2*>(smem + ad) = v;
                        }
                    }
                }
        }
    }
    __syncthreads();   // final scatter complete

    // ---- epilogue: smem acc -> out, + BN partials ----
    {
        const int pp = tid & 63;     // pair (2 channels)
        const int g  = tid >> 6;     // row group 0..7 (32 rows each)
        float s0 = 0.f, s1 = 0.f, q0 = 0.f, q1 = 0.f;
        #pragma unroll 4
        for (int rr = 0; rr < 32; rr++) {
            int r = g * 32 + rr;
            float2 v = *reinterpret_cast<float2*>(smem + acc_off(r, pp));
            int row = row0 + r;
            if (row < N_ACT)
                *reinterpret_cast<float2*>(out + (size_t)row * CDIM + pp * 2) = v;
            s0 += v.x; s1 += v.y;
            q0 = fmaf(v.x, v.x, q0);
            q1 = fmaf(v.y, v.y, q1);
        }
        __syncthreads();
        float4* red = reinterpret_cast<float4*>(smem + OFF_A);   // [8][64]
        red[g * 64 + pp] = make_float4(s0, s1, q0, q1);
        __syncthreads();
        if (tid < 64) {
            float ts0 = 0.f, ts1 = 0.f, tq0 = 0.f, tq1 = 0.f;
            #pragma unroll
            for (int gg = 0; gg < 8; gg++) {
                float4 v = red[gg * 64 + tid];
                ts0 += v.x; ts1 += v.y; tq0 += v.z; tq1 += v.w;
            }
            g_psum[blockIdx.x * CDIM + tid * 2]     = ts0;
            g_psum[blockIdx.x * CDIM + tid * 2 + 1] = ts1;
            g_psq [blockIdx.x * CDIM + tid * 2]     = tq0;
            g_psq [blockIdx.x * CDIM + tid * 2 + 1] = tq1;
        }
    }
}

// ============================================================
// Kernel 3: finalize BN scale/bias (parallel, deterministic tree)
// ============================================================
__global__ void bn_final_kernel(const float* __restrict__ gamma, const float* __restrict__ beta) {
    __shared__ float ss[256], sq[256];
    int c = blockIdx.x;
    int t = threadIdx.x;
    float s = 0.f, q = 0.f;
    for (int b = t; b < NBLK; b += 256) {
        s += g_psum[b * CDIM + c];
        q += g_psq [b * CDIM + c];
    }
    ss[t] = s; sq[t] = q;
    __syncthreads();
    #pragma unroll
    for (int st = 128; st > 0; st >>= 1) {
        if (t < st) { ss[t] += ss[t + st]; sq[t] += sq[t + st]; }
        __syncthreads();
    }
    if (t == 0) {
        float mean = ss[0] / (float)N_ACT;
        float var  = sq[0] / (float)N_ACT - mean * mean;
        float sc   = gamma[c] * rsqrtf(var + BN_EPS);
        g_scale[c] = sc;
        g_bias[c]  = beta[c] - mean * sc;
    }
}

// ============================================================
// Kernel 4: apply BN + ReLU elementwise
// ============================================================
__global__ void bn_apply_kernel(float* __restrict__ out) {
    size_t idx = (size_t)blockIdx.x * blockDim.x + threadIdx.x;
    if (idx >= (size_t)N_ACT * CDIM / 4) return;
    int c4 = (int)(idx & 31);
    float4 v  = reinterpret_cast<float4*>(out)[idx];
    float4 sc = reinterpret_cast<float4*>(g_scale)[c4];
    float4 bi = reinterpret_cast<float4*>(g_bias)[c4];
    v.x = fmaxf(fmaf(v.x, sc.x, bi.x), 0.f);
    v.y = fmaxf(fmaf(v.y, sc.y, bi.y), 0.f);
    v.z = fmaxf(fmaf(v.z, sc.z, bi.z), 0.f);
    v.w = fmaxf(fmaf(v.w, sc.w, bi.w), 0.f);
    reinterpret_cast<float4*>(out)[idx] = v;
}

// ============================================================
// Launch
// ============================================================
extern "C" void kernel_launch(void* const* d_in, const int* in_sizes, int n_in,
                              void* d_out, int out_size) {
    const float* features = (const float*)d_in[0];
    const int*   nbr      = (const int*)d_in[1];
    const float* W        = (const float*)d_in[2];
    const float* gamma    = (const float*)d_in[3];
    const float* beta     = (const float*)d_in[4];
    float* out = (float*)d_out;

    cudaFuncSetAttribute((const void*)conv_kernel,
                         cudaFuncAttributeMaxDynamicSharedMemorySize, SMEM_TOTAL);

    const int chunks = N_ACT * CDIM / 4;
    cvt_features_kernel<<<(chunks + 255) / 256, 256>>>(features);
    cvt_w_kernel<<<KOFF * CDIM * CDIM / 256, 256>>>(W);
    dummy_kernel<<<1, 32>>>();   // shifts conv into ncu's capture slot
    conv_kernel<<<NBLK, CONV_THREADS, SMEM_TOTAL>>>(nbr, out);
    bn_final_kernel<<<CDIM, 256>>>(gamma, beta);
    bn_apply_kernel<<<(chunks + 255) / 256, 256>>>(out);
}

// round 12
// speedup vs baseline: 1.4075x; 1.0275x over previous
#include <cuda_runtime.h>
#include <cuda_fp16.h>
#include <cstdint>
#include <cstddef>

// ============================================================
// Problem constants
// ============================================================
constexpr int N_ACT = 200000;
constexpr int CDIM  = 128;
constexpr int KOFF  = 27;
constexpr float BN_EPS = 1e-4f;

constexpr int BM           = 256;                       // output rows per CTA
constexpr int NBLK         = (N_ACT + BM - 1) / BM;     // 782
constexpr int CONV_THREADS = 512;                       // 16 warps

// SMEM layout (dynamic); A/B tiles use 256B-stride XOR swizzle
constexpr uint32_t OFF_ACC   = 0;                       // 256 x 128 fp32, rotated pairs
constexpr uint32_t ACC_B     = 256u * 512u;             // 131072
constexpr uint32_t OFF_A     = OFF_ACC + ACC_B;         // 131072 ; 2 x 64x256
constexpr uint32_t A_TILE    = 64u * 256u;              // 16384
constexpr uint32_t OFF_B     = OFF_A + 2u * A_TILE;     // 163840 ; 2 x 128x256
constexpr uint32_t B_TILE    = 128u * 256u;             // 32768
constexpr uint32_t OFF_STRIP = OFF_B + 2u * B_TILE;     // 229376 ; 2 x 64 ints
constexpr uint32_t OFF_CNT   = OFF_STRIP + 512;         // 229888 ; 27 ints (pad 112)
constexpr uint32_t OFF_WORK  = OFF_CNT + 112;           // 230000 ; up to 108 ints
constexpr uint32_t OFF_NW    = OFF_WORK + 448;          // 230448
constexpr uint32_t SMEM_TOTAL = OFF_NW + 16;            // 230464  (< 232448 limit)

// ============================================================
// Device scratch
// ============================================================
__device__ __align__(16) __half g_Af16[(size_t)N_ACT * CDIM];          // 51.2 MB
__device__ __align__(16) __half g_Wt16[(size_t)KOFF * CDIM * CDIM];    // [k][cout][cin]
__device__ int g_cidx[(size_t)NBLK * KOFF * BM];        // compact rulebook (idx | row<<18)
__device__ int g_cnt [NBLK * KOFF];
__device__ float g_psum[NBLK * CDIM];
__device__ float g_psq [NBLK * CDIM];
__device__ __align__(16) float g_scale[CDIM];
__device__ __align__(16) float g_bias [CDIM];

// ============================================================
// Helpers
// ============================================================
__device__ __forceinline__ uint32_t smem_u32(const void* p) {
    uint32_t a;
    asm("{ .reg .u64 t; cvta.to.shared.u64 t, %1; cvt.u32.u64 %0, t; }" : "=r"(a) : "l"(p));
    return a;
}
__device__ __forceinline__ void cp_async16(uint32_t dst, const void* src) {
    asm volatile("cp.async.cg.shared.global [%0], [%1], 16;" :: "r"(dst), "l"(src) : "memory");
}
__device__ __forceinline__ void sts_fill16(uint32_t dst, uint32_t v) {
    asm volatile("st.shared.v4.b32 [%0], {%1, %1, %1, %1};" :: "r"(dst), "r"(v) : "memory");
}
__device__ __forceinline__ void cp_commit() {
    asm volatile("cp.async.commit_group;" ::: "memory");
}
template <int N>
__device__ __forceinline__ void cp_wait() {
    asm volatile("cp.async.wait_group %0;" :: "n"(N) : "memory");
}
__device__ __forceinline__ void ldsm_x4(uint32_t* r, uint32_t addr) {
    asm volatile("ldmatrix.sync.aligned.m8n8.x4.shared.b16 {%0,%1,%2,%3}, [%4];"
                 : "=r"(r[0]), "=r"(r[1]), "=r"(r[2]), "=r"(r[3]) : "r"(addr));
}
__device__ __forceinline__ void mma16816(float* d, const uint32_t* a, const uint32_t* b) {
    asm volatile(
        "mma.sync.aligned.m16n8k16.row.col.f32.f16.f16.f32 "
        "{%0,%1,%2,%3}, {%4,%5,%6,%7}, {%8,%9}, {%0,%1,%2,%3};"
        : "+f"(d[0]), "+f"(d[1]), "+f"(d[2]), "+f"(d[3])
        : "r"(a[0]), "r"(a[1]), "r"(a[2]), "r"(a[3]), "r"(b[0]), "r"(b[1]));
}
// 256B-stride tile swizzle (R10-verified): 16B chunk c (0..15), XOR low3 with row&7.
__device__ __forceinline__ uint32_t swz(int row, int c) {
    return (uint32_t)row * 256u + 16u * (uint32_t)((c & 8) | ((c & 7) ^ (row & 7)));
}
// Accumulator: row r (0..255), pair pp (0..63), rotated across banks (R11-verified).
__device__ __forceinline__ uint32_t acc_off(int r, int pp) {
    return OFF_ACC + (uint32_t)r * 512u + (uint32_t)(((pp + r * 8) & 63) << 3);
}

// ============================================================
// Kernel 1a: features fp32 -> fp16
// ============================================================
__global__ void cvt_features_kernel(const float* __restrict__ f) {
    size_t idx = (size_t)blockIdx.x * blockDim.x + threadIdx.x;
    if (idx >= (size_t)N_ACT * CDIM / 4) return;
    float4 v = reinterpret_cast<const float4*>(f)[idx];
    __half2* dst = reinterpret_cast<__half2*>(g_Af16) + 2 * idx;
    dst[0] = __floats2half2_rn(v.x, v.y);
    dst[1] = __floats2half2_rn(v.z, v.w);
}

// ============================================================
// Kernel 1b: W [k][cin][cout] fp32 -> Wt [k][cout][cin] fp16
// ============================================================
__global__ void cvt_w_kernel(const float* __restrict__ W) {
    int m = blockIdx.x * blockDim.x + threadIdx.x;
    int k   = m >> 14;
    int rem = m & 16383;
    int c   = rem >> 7;   // cout
    int j   = rem & 127;  // cin
    g_Wt16[m] = __float2half_rn(W[(k << 14) + (j << 7) + c]);
}

// ============================================================
// Kernel 1c: build global compact rulebook, one block per (row-block, k)
// ============================================================
__global__ void compact_kernel(const int* __restrict__ nbr) {
    const int b = blockIdx.x;
    const int k = blockIdx.y;
    const int t = threadIdx.x;       // 256 threads
    const int lid = t & 31;
    const int w = t >> 5;            // 8 warps
    __shared__ int wcnt[8];

    int r = b * BM + t;
    int idx = (r < N_ACT) ? nbr[(size_t)k * N_ACT + r] : -1;
    bool valid = (idx >= 0);
    unsigned bal = __ballot_sync(0xFFFFFFFFu, valid);
    if (lid == 0) wcnt[w] = __popc(bal);
    __syncthreads();
    int base = 0;
    #pragma unroll
    for (int j = 0; j < 8; j++) base += (j < w) ? wcnt[j] : 0;
    int pos = base + __popc(bal & ((1u << lid) - 1u));
    if (valid) g_cidx[((size_t)b * KOFF + k) * BM + pos] = idx | (t << 18);
    if (t == 0) {
        int tot = 0;
        #pragma unroll
        for (int j = 0; j < 8; j++) tot += wcnt[j];
        g_cnt[b * KOFF + k] = tot;
    }
}

// ============================================================
// Dummy kernel (slot-shifter so ncu captures conv_kernel)
// ============================================================
__global__ void dummy_kernel() {}

// ============================================================
// Kernel 2: compacted sparse conv; double-buffered A AND B, one barrier/unit
// ============================================================
__global__ void __launch_bounds__(CONV_THREADS, 1)
conv_kernel(float* __restrict__ out) {
    extern __shared__ char smem[];
    const uint32_t sb = smem_u32(smem);
    const int tid = threadIdx.x;
    const int wid = tid >> 5;
    const int lid = tid & 31;
    const int b = blockIdx.x;
    const int row0 = b * BM;

    int* s_strip = reinterpret_cast<int*>(smem + OFF_STRIP);   // [2][64]
    int* s_cnt   = reinterpret_cast<int*>(smem + OFF_CNT);
    int* s_work  = reinterpret_cast<int*>(smem + OFF_WORK);
    int* s_nw    = reinterpret_cast<int*>(smem + OFF_NW);

    // ---- zero the smem accumulator (32768 floats) + fetch cnts ----
    {
        float4* a4 = reinterpret_cast<float4*>(smem + OFF_ACC);
        #pragma unroll
        for (int i = 0; i < 16; i++)
            a4[tid + i * CONV_THREADS] = make_float4(0.f, 0.f, 0.f, 0.f);
    }
    if (tid < KOFF) s_cnt[tid] = g_cnt[b * KOFF + tid];
    __syncthreads();
    // worklist entry: (k<<3) | (s<<1) | last_unit_of_k
    if (tid == 0) {
        int nw = 0;
        for (int k = 0; k < KOFF; k++) {
            int ns = (s_cnt[k] + 63) >> 6;
            for (int s = 0; s < ns; s++)
                s_work[nw++] = (k << 3) | (s << 1) | ((s == ns - 1) ? 1 : 0);
        }
        *s_nw = nw;
    }
    __syncthreads();
    const int nwork = *s_nw;

    // ---- tile loaders ----
    // A: 64 compact rows x 256B; thread -> (row p = tid>>3, chunks o and o+8).
    //    Thread o==0 of each row also stashes the packed entry into the strip.
    auto load_A = [&](int w, int buf) {
        int e = s_work[w];
        int k = e >> 3, s = (e >> 1) & 3;
        int cnt = s_cnt[k];
        int p = tid >> 3;
        int o = tid & 7;
        uint32_t dst0 = sb + OFF_A + (uint32_t)buf * A_TILE + swz(p, o);
        uint32_t dst1 = sb + OFF_A + (uint32_t)buf * A_TILE + swz(p, o + 8);
        int pos = s * 64 + p;
        if (pos < cnt) {
            int ent = __ldg(&g_cidx[((size_t)b * KOFF + k) * BM + pos]);
            if (o == 0) s_strip[buf * 64 + p] = ent;
            const char* src = (const char*)g_Af16 + (size_t)((uint32_t)ent & 0x3FFFFu) * 256 + o * 16;
            cp_async16(dst0, src);
            cp_async16(dst1, src + 128);
        } else {
            sts_fill16(dst0, 0u);
            sts_fill16(dst1, 0u);
        }
    };
    // B: 128 rows x 256B; thread -> (row n = tid>>2, 4 chunks)
    auto load_B = [&](int k, int buf) {
        int n = tid >> 2;
        int qq = tid & 3;
        const char* src = (const char*)g_Wt16 + ((size_t)k * 128 + n) * 256;
        uint32_t base = sb + OFF_B + (uint32_t)buf * B_TILE;
        #pragma unroll
        for (int j = 0; j < 4; j++) {
            int c = qq * 4 + j;
            cp_async16(base + swz(n, c), src + c * 16);
        }
    };

    // ---- per-lane fragment pieces (16 warps: 2M x 8N, warp tile 32x16) ----
    const int mg = wid & 1;
    const int ng = wid >> 1;
    const int a_r0 = mg * 32 + (lid & 15);
    const int a_cs = lid >> 4;                 // A chunk parity
    const int b_r  = ng * 16 + (lid & 7) + ((lid & 16) ? 8 : 0);
    const int b_cs = (lid >> 3) & 1;           // B chunk parity
    const int p_base  = mg * 32 + (lid >> 2);  // compact slot base
    const int pp_base = ng * 8 + (lid & 3);    // acc pair base

    // ---- prime: B(k0) buf0, A(unit 0) buf0 ----
    load_B(s_work[0] >> 3, 0);
    load_A(0, 0);
    cp_commit();
    int bbuf = 0;

    #pragma unroll 1
    for (int w = 0; w < nwork; w++) {
        const int e = s_work[w];
        const int k = e >> 3, s = (e >> 1) & 3;
        const bool last = (e & 1) != 0;
        const int abuf = w & 1;
        const int cnt = s_cnt[k];

        cp_wait<0>();      // A(w) [+B group if pending] complete
        __syncthreads();   // S1: all warps done GEMM(w-1)+scatter(w-1); tiles visible

        // issue next loads (covered by this unit's GEMM + scatter)
        if (w + 1 < nwork) {
            load_A(w + 1, abuf ^ 1);
            if (last) load_B(s_work[w + 1] >> 3, bbuf ^ 1);
            cp_commit();
        }

        // ---- 64x128x128 compact GEMM (warp tile 32x16) ----
        float facc[2][2][4];
        #pragma unroll
        for (int a = 0; a < 2; a++)
            #pragma unroll
            for (int b2 = 0; b2 < 2; b2++)
                #pragma unroll
                for (int c = 0; c < 4; c++) facc[a][b2][c] = 0.f;
        {
            const uint32_t ab  = sb + OFF_A + (uint32_t)abuf * A_TILE;
            const uint32_t bbs = sb + OFF_B + (uint32_t)bbuf * B_TILE;
            #pragma unroll
            for (int ks = 0; ks < 8; ks++) {
                uint32_t af0[4], af1[4], t[4];
                int ca = ks * 2 + a_cs;
                int cb = ks * 2 + b_cs;
                ldsm_x4(af0, ab + swz(a_r0, ca));
                ldsm_x4(af1, ab + swz(a_r0 + 16, ca));
                ldsm_x4(t, bbs + swz(b_r, cb));
                uint32_t bf0[2] = {t[0], t[1]};
                uint32_t bf1[2] = {t[2], t[3]};
                mma16816(facc[0][0], af0, bf0);
                mma16816(facc[0][1], af0, bf1);
                mma16816(facc[1][0], af1, bf0);
                mma16816(facc[1][1], af1, bf1);
            }
        }

        // ---- direct scatter-add into smem accumulator (strip-cached rows) ----
        {
            const int base_s = s * 64;
            #pragma unroll
            for (int mf = 0; mf < 2; mf++)
                #pragma unroll
                for (int h = 0; h < 2; h++) {
                    int slot = p_base + mf * 16 + h * 8;
                    if (base_s + slot < cnt) {
                        int r = ((uint32_t)s_strip[abuf * 64 + slot]) >> 18;
                        #pragma unroll
                        for (int nf = 0; nf < 2; nf++) {
                            uint32_t ad = acc_off(r, pp_base + nf * 4);
                            float2 v = *reinterpret_cast<float2*>(smem + ad);
                            v.x += facc[mf][nf][2 * h];
                            v.y += facc[mf][nf][2 * h + 1];
                            *reinterpret_cast<float2*>(smem + ad) = v;
                        }
                    }
                }
        }
        if (last) bbuf ^= 1;
    }
    __syncthreads();   // final scatter complete

    // ---- epilogue: smem acc -> out, + BN partials ----
    {
        const int pp = tid & 63;     // pair (2 channels)
        const int g  = tid >> 6;     // row group 0..7 (32 rows each)
        float s0 = 0.f, s1 = 0.f, q0 = 0.f, q1 = 0.f;
        #pragma unroll 4
        for (int rr = 0; rr < 32; rr++) {
            int r = g * 32 + rr;
            float2 v = *reinterpret_cast<float2*>(smem + acc_off(r, pp));
            int row = row0 + r;
            if (row < N_ACT)
                *reinterpret_cast<float2*>(out + (size_t)row * CDIM + pp * 2) = v;
            s0 += v.x; s1 += v.y;
            q0 = fmaf(v.x, v.x, q0);
            q1 = fmaf(v.y, v.y, q1);
        }
        __syncthreads();
        float4* red = reinterpret_cast<float4*>(smem + OFF_A);   // [8][64]
        red[g * 64 + pp] = make_float4(s0, s1, q0, q1);
        __syncthreads();
        if (tid < 64) {
            float ts0 = 0.f, ts1 = 0.f, tq0 = 0.f, tq1 = 0.f;
            #pragma unroll
            for (int gg = 0; gg < 8; gg++) {
                float4 v = red[gg * 64 + tid];
                ts0 += v.x; ts1 += v.y; tq0 += v.z; tq1 += v.w;
            }
            g_psum[b * CDIM + tid * 2]     = ts0;
            g_psum[b * CDIM + tid * 2 + 1] = ts1;
            g_psq [b * CDIM + tid * 2]     = tq0;
            g_psq [b * CDIM + tid * 2 + 1] = tq1;
        }
    }
}

// ============================================================
// Kernel 3: finalize BN scale/bias (parallel, deterministic tree)
// ============================================================
__global__ void bn_final_kernel(const float* __restrict__ gamma, const float* __restrict__ beta) {
    __shared__ float ss[256], sq[256];
    int c = blockIdx.x;
    int t = threadIdx.x;
    float s = 0.f, q = 0.f;
    for (int b = t; b < NBLK; b += 256) {
        s += g_psum[b * CDIM + c];
        q += g_psq [b * CDIM + c];
    }
    ss[t] = s; sq[t] = q;
    __syncthreads();
    #pragma unroll
    for (int st = 128; st > 0; st >>= 1) {
        if (t < st) { ss[t] += ss[t + st]; sq[t] += sq[t + st]; }
        __syncthreads();
    }
    if (t == 0) {
        float mean = ss[0] / (float)N_ACT;
        float var  = sq[0] / (float)N_ACT - mean * mean;
        float sc   = gamma[c] * rsqrtf(var + BN_EPS);
        g_scale[c] = sc;
        g_bias[c]  = beta[c] - mean * sc;
    }
}

// ============================================================
// Kernel 4: apply BN + ReLU elementwise
// ============================================================
__global__ void bn_apply_kernel(float* __restrict__ out) {
    size_t idx = (size_t)blockIdx.x * blockDim.x + threadIdx.x;
    if (idx >= (size_t)N_ACT * CDIM / 4) return;
    int c4 = (int)(idx & 31);
    float4 v  = reinterpret_cast<float4*>(out)[idx];
    float4 sc = reinterpret_cast<float4*>(g_scale)[c4];
    float4 bi = reinterpret_cast<float4*>(g_bias)[c4];
    v.x = fmaxf(fmaf(v.x, sc.x, bi.x), 0.f);
    v.y = fmaxf(fmaf(v.y, sc.y, bi.y), 0.f);
    v.z = fmaxf(fmaf(v.z, sc.z, bi.z), 0.f);
    v.w = fmaxf(fmaf(v.w, sc.w, bi.w), 0.f);
    reinterpret_cast<float4*>(out)[idx] = v;
}

// ============================================================
// Launch
// ============================================================
extern "C" void kernel_launch(void* const* d_in, const int* in_sizes, int n_in,
                              void* d_out, int out_size) {
    const float* features = (const float*)d_in[0];
    const int*   nbr      = (const int*)d_in[1];
    const float* W        = (const float*)d_in[2];
    const float* gamma    = (const float*)d_in[3];
    const float* beta     = (const float*)d_in[4];
    float* out = (float*)d_out;

    cudaFuncSetAttribute((const void*)conv_kernel,
                         cudaFuncAttributeMaxDynamicSharedMemorySize, SMEM_TOTAL);

    const int chunks = N_ACT * CDIM / 4;
    cvt_features_kernel<<<(chunks + 255) / 256, 256>>>(features);
    cvt_w_kernel<<<KOFF * CDIM * CDIM / 256, 256>>>(W);
    compact_kernel<<<dim3(NBLK, KOFF), 256>>>(nbr);
    dummy_kernel<<<1, 32>>>();   // keeps conv in ncu's capture slot
    conv_kernel<<<NBLK, CONV_THREADS, SMEM_TOTAL>>>(out);
    bn_final_kernel<<<CDIM, 256>>>(gamma, beta);
    bn_apply_kernel<<<(chunks + 255) / 256, 256>>>(out);
}